// round 1
// baseline (speedup 1.0000x reference)
#include <cuda_runtime.h>
#include <math.h>

// Problem dims
#define BB   128
#define TT   512
#define FF   784
#define HH   256
#define NG   1024   // 4*H
#define CC   10
#define BN_EPS 1e-3f

// Scratch (device globals; no runtime allocation allowed)
__device__ float g_xw[(size_t)BB * TT * NG];  // 256 MiB: precomputed input projection
__device__ float g_hs[(size_t)BB * TT * HH];  //  64 MiB: all hidden states

// ---------------------------------------------------------------------------
// K1: xw = x @ kernel + bias      [M=B*T, K=F] x [K=F, N=4H]
// Classic 128x128 tile, BK=8, 256 threads, 8x8 per-thread register blocking.
// ---------------------------------------------------------------------------
__global__ __launch_bounds__(256, 2)
void gemm_xw_kernel(const float* __restrict__ A,     // [M, F]
                    const float* __restrict__ Bm,    // [F, NG]
                    const float* __restrict__ bias)  // [NG]
{
    __shared__ float As[8][128];
    __shared__ float Bs[8][128];

    const int bx  = blockIdx.x;          // N tile (8)
    const int by  = blockIdx.y;          // M tile (512)
    const int tid = threadIdx.x;

    // A tile loaders: 128 rows x 8 cols = 256 float4 (one per thread)
    const int a_row = tid >> 1;
    const int a_col = (tid & 1) * 4;
    // B tile loaders: 8 rows x 128 cols = 256 float4
    const int b_row = tid >> 5;
    const int b_col = (tid & 31) * 4;
    // compute mapping: 16x16 threads, 8x8 outputs each
    const int ty = tid >> 4;
    const int tx = tid & 15;

    const float* Aptr = A  + (size_t)(by * 128 + a_row) * FF + a_col;
    const float* Bptr = Bm + (size_t)b_row * NG + bx * 128 + b_col;

    float acc[8][8];
#pragma unroll
    for (int i = 0; i < 8; i++)
#pragma unroll
        for (int j = 0; j < 8; j++) acc[i][j] = 0.f;

    for (int k0 = 0; k0 < FF; k0 += 8) {   // 98 iterations
        float4 av = *(const float4*)(Aptr + k0);
        float4 bv = *(const float4*)(Bptr + (size_t)k0 * NG);
        __syncthreads();
        As[a_col + 0][a_row] = av.x;
        As[a_col + 1][a_row] = av.y;
        As[a_col + 2][a_row] = av.z;
        As[a_col + 3][a_row] = av.w;
        *(float4*)&Bs[b_row][b_col] = bv;
        __syncthreads();
#pragma unroll
        for (int kk = 0; kk < 8; kk++) {
            float4 a0 = *(const float4*)&As[kk][ty * 8];
            float4 a1 = *(const float4*)&As[kk][ty * 8 + 4];
            float4 b0 = *(const float4*)&Bs[kk][tx * 8];
            float4 b1 = *(const float4*)&Bs[kk][tx * 8 + 4];
            float ar[8] = {a0.x, a0.y, a0.z, a0.w, a1.x, a1.y, a1.z, a1.w};
            float br[8] = {b0.x, b0.y, b0.z, b0.w, b1.x, b1.y, b1.z, b1.w};
#pragma unroll
            for (int i = 0; i < 8; i++)
#pragma unroll
                for (int j = 0; j < 8; j++)
                    acc[i][j] += ar[i] * br[j];
        }
    }

    const int row0 = by * 128 + ty * 8;
    const int col0 = bx * 128 + tx * 8;
    float4 bia0 = *(const float4*)&bias[col0];
    float4 bia1 = *(const float4*)&bias[col0 + 4];
#pragma unroll
    for (int i = 0; i < 8; i++) {
        float4 o0, o1;
        o0.x = acc[i][0] + bia0.x; o0.y = acc[i][1] + bia0.y;
        o0.z = acc[i][2] + bia0.z; o0.w = acc[i][3] + bia0.w;
        o1.x = acc[i][4] + bia1.x; o1.y = acc[i][5] + bia1.y;
        o1.z = acc[i][6] + bia1.z; o1.w = acc[i][7] + bia1.w;
        float* crow = g_xw + (size_t)(row0 + i) * NG + col0;
        *(float4*)(crow)     = o0;
        *(float4*)(crow + 4) = o1;
    }
}

// ---------------------------------------------------------------------------
// K2: peephole LSTM recurrence. One CTA owns BPC batch rows for all T steps.
// Thread `tid` owns hidden unit `tid`: it accumulates z for gate columns
// {tid, tid+256, tid+512, tid+768} -> gate math entirely in registers.
// h lives in smem (read by all threads next step); c lives in registers.
// rec_kernel (1 MB) streams from L2 every step (fits L2, shared by all CTAs).
// ---------------------------------------------------------------------------
#define BPC 2
__global__ __launch_bounds__(256, 1)
void lstm_kernel(const float* __restrict__ xw,
                 const float* __restrict__ rec,     // [H, 4H] row-major
                 const float* __restrict__ wci_p,
                 const float* __restrict__ wcf_p,
                 const float* __restrict__ wco_p,
                 float* __restrict__ hs)
{
    const int tid = threadIdx.x;           // 0..255  == hidden index
    const int b0  = blockIdx.x * BPC;

    __shared__ float h_s[BPC][HH];
    float c_r[BPC];
#pragma unroll
    for (int b = 0; b < BPC; b++) { h_s[b][tid] = 0.f; c_r[b] = 0.f; }

    const float wci = wci_p[tid];
    const float wcf = wcf_p[tid];
    const float wco = wco_p[tid];
    __syncthreads();

    for (int t = 0; t < TT; t++) {
        float acc[BPC][4];
#pragma unroll
        for (int b = 0; b < BPC; b++) {
            const float* xrow = xw + (size_t)((b0 + b) * TT + t) * NG;
#pragma unroll
            for (int g = 0; g < 4; g++)
                acc[b][g] = xrow[g * HH + tid];
        }

#pragma unroll 4
        for (int k = 0; k < HH; k++) {
            const float* rrow = rec + (size_t)k * NG;
            float w0 = rrow[tid];
            float w1 = rrow[HH + tid];
            float w2 = rrow[2 * HH + tid];
            float w3 = rrow[3 * HH + tid];
#pragma unroll
            for (int b = 0; b < BPC; b++) {
                float hk = h_s[b][k];
                acc[b][0] += w0 * hk;
                acc[b][1] += w1 * hk;
                acc[b][2] += w2 * hk;
                acc[b][3] += w3 * hk;
            }
        }

        __syncthreads();   // done reading previous h
#pragma unroll
        for (int b = 0; b < BPC; b++) {
            float cp = c_r[b];
            float ig = 1.f / (1.f + __expf(-(acc[b][0] + cp * wci)));
            float fg = 1.f / (1.f + __expf(-(acc[b][1] + cp * wcf)));
            float cn = fg * cp + ig * tanhf(acc[b][2]);
            float og = 1.f / (1.f + __expf(-(acc[b][3] + cn * wco)));
            float hn = og * tanhf(cn);
            c_r[b] = cn;
            h_s[b][tid] = hn;
            hs[(size_t)((b0 + b) * TT + t) * HH + tid] = hn;
        }
        __syncthreads();   // h visible for next step
    }
}

// ---------------------------------------------------------------------------
// K3: BN(inference) -> tanh -> [H x C] dense. One warp per (b,t) row.
// ---------------------------------------------------------------------------
__global__ __launch_bounds__(256)
void head_kernel(const float* __restrict__ hs,
                 const float* __restrict__ gamma,
                 const float* __restrict__ beta,
                 const float* __restrict__ mean,
                 const float* __restrict__ var,
                 const float* __restrict__ fc,     // [H, C]
                 float* __restrict__ out)          // [B*T, C]
{
    const int warp = (blockIdx.x * blockDim.x + threadIdx.x) >> 5;
    const int lane = threadIdx.x & 31;
    if (warp >= BB * TT) return;

    const float* hrow = hs + (size_t)warp * HH;
    float acc[CC];
#pragma unroll
    for (int c = 0; c < CC; c++) acc[c] = 0.f;

#pragma unroll
    for (int kk = 0; kk < HH / 32; kk++) {
        int k = kk * 32 + lane;
        float s = rsqrtf(var[k] + BN_EPS) * gamma[k];
        float v = tanhf((hrow[k] - mean[k]) * s + beta[k]);
#pragma unroll
        for (int c = 0; c < CC; c++)
            acc[c] += v * fc[k * CC + c];
    }
#pragma unroll
    for (int c = 0; c < CC; c++) {
#pragma unroll
        for (int off = 16; off > 0; off >>= 1)
            acc[c] += __shfl_xor_sync(0xffffffffu, acc[c], off);
    }
    if (lane == 0) {
        float* orow = out + (size_t)warp * CC;
#pragma unroll
        for (int c = 0; c < CC; c++) orow[c] = acc[c];
    }
}

// ---------------------------------------------------------------------------
extern "C" void kernel_launch(void* const* d_in, const int* in_sizes, int n_in,
                              void* d_out, int out_size)
{
    const float* x      = (const float*)d_in[0];   // [B,T,F]
    const float* kernel = (const float*)d_in[1];   // [F,4H]
    const float* rec    = (const float*)d_in[2];   // [H,4H]
    const float* bias   = (const float*)d_in[3];   // [4H]
    const float* w_ci   = (const float*)d_in[4];
    const float* w_cf   = (const float*)d_in[5];
    const float* w_co   = (const float*)d_in[6];
    const float* gamma  = (const float*)d_in[7];
    const float* beta   = (const float*)d_in[8];
    const float* mmean  = (const float*)d_in[9];
    const float* mvar   = (const float*)d_in[10];
    const float* fc_w   = (const float*)d_in[11];  // [H,C]
    float* out = (float*)d_out;                    // [B,T,C]

    float* xw_p;
    float* hs_p;
    cudaGetSymbolAddress((void**)&xw_p, g_xw);
    cudaGetSymbolAddress((void**)&hs_p, g_hs);

    // K1: input projection GEMM  [65536 x 784] x [784 x 1024]
    dim3 g1(NG / 128, (BB * TT) / 128);
    gemm_xw_kernel<<<g1, 256>>>(x, kernel, bias);

    // K2: recurrence, 64 CTAs x 256 threads
    lstm_kernel<<<BB / BPC, 256>>>(xw_p, rec, w_ci, w_cf, w_co, hs_p);

    // K3: head, one warp per row
    int rows = BB * TT;
    head_kernel<<<(rows * 32 + 255) / 256, 256>>>(hs_p, gamma, beta, mmean, mvar, fc_w, out);
}

// round 2
// speedup vs baseline: 1.6691x; 1.6691x over previous
#include <cuda_runtime.h>
#include <math.h>
#include <stdint.h>

// Problem dims
#define BB   128
#define TT   512
#define FF   784
#define HH   256
#define NG   1024   // 4*H
#define CC   10
#define BN_EPS 1e-3f

// Scratch (device globals; no runtime allocation allowed)
__device__ float  g_xw[(size_t)BB * TT * NG];   // 256 MiB: input projection
__device__ float  g_hs[(size_t)BB * TT * HH];   //  64 MiB: hidden states
__device__ float4 g_rw[(size_t)HH * HH];        //   1 MiB: packed rec weights [k][u]{i,f,c,o}

// ---------------------------------------------------------------------------
// K0: pack rec_kernel [H,4H] -> rw[k][u] = {rec[k][u], rec[k][H+u], rec[k][2H+u], rec[k][3H+u]}
// ---------------------------------------------------------------------------
__global__ void pack_rec_kernel(const float* __restrict__ rec, float4* __restrict__ rw)
{
    int idx = blockIdx.x * blockDim.x + threadIdx.x;   // k*256 + u
    if (idx >= HH * HH) return;
    int k = idx >> 8;
    int u = idx & 255;
    const float* r = rec + (size_t)k * NG;
    rw[idx] = make_float4(r[u], r[HH + u], r[2 * HH + u], r[3 * HH + u]);
}

// ---------------------------------------------------------------------------
// K1: xw = x @ kernel + bias   [65536 x 784] x [784 x 1024]
// 128x128 tile, BK=8, 256 threads, 8x8 micro-tile, double-buffered smem.
// ---------------------------------------------------------------------------
__global__ __launch_bounds__(256, 2)
void gemm_xw_kernel(const float* __restrict__ A,     // [M, F]
                    const float* __restrict__ Bm,    // [F, NG]
                    const float* __restrict__ bias)  // [NG]
{
    __shared__ float As[2][8][128];
    __shared__ float Bs[2][8][128];

    const int bx  = blockIdx.x;
    const int by  = blockIdx.y;
    const int tid = threadIdx.x;

    const int a_row = tid >> 1;
    const int a_col = (tid & 1) * 4;
    const int b_row = tid >> 5;
    const int b_col = (tid & 31) * 4;
    const int ty = tid >> 4;
    const int tx = tid & 15;

    const float* Aptr = A  + (size_t)(by * 128 + a_row) * FF + a_col;
    const float* Bptr = Bm + (size_t)b_row * NG + bx * 128 + b_col;

    float acc[8][8];
#pragma unroll
    for (int i = 0; i < 8; i++)
#pragma unroll
        for (int j = 0; j < 8; j++) acc[i][j] = 0.f;

    // prologue: stage k0 = 0 into buffer 0
    {
        float4 av = *(const float4*)(Aptr);
        float4 bv = *(const float4*)(Bptr);
        As[0][a_col + 0][a_row] = av.x;
        As[0][a_col + 1][a_row] = av.y;
        As[0][a_col + 2][a_row] = av.z;
        As[0][a_col + 3][a_row] = av.w;
        *(float4*)&Bs[0][b_row][b_col] = bv;
    }
    __syncthreads();

    int buf = 0;
    for (int k0 = 8; k0 < FF; k0 += 8) {   // 97 steady iterations
        // load-ahead for next stage
        float4 av = *(const float4*)(Aptr + k0);
        float4 bv = *(const float4*)(Bptr + (size_t)k0 * NG);

        // compute current stage
#pragma unroll
        for (int kk = 0; kk < 8; kk++) {
            float4 a0 = *(const float4*)&As[buf][kk][ty * 8];
            float4 a1 = *(const float4*)&As[buf][kk][ty * 8 + 4];
            float4 b0 = *(const float4*)&Bs[buf][kk][tx * 8];
            float4 b1 = *(const float4*)&Bs[buf][kk][tx * 8 + 4];
            float ar[8] = {a0.x, a0.y, a0.z, a0.w, a1.x, a1.y, a1.z, a1.w};
            float br[8] = {b0.x, b0.y, b0.z, b0.w, b1.x, b1.y, b1.z, b1.w};
#pragma unroll
            for (int i = 0; i < 8; i++)
#pragma unroll
                for (int j = 0; j < 8; j++)
                    acc[i][j] += ar[i] * br[j];
        }

        // stage into the other buffer (not in use)
        int nb = buf ^ 1;
        As[nb][a_col + 0][a_row] = av.x;
        As[nb][a_col + 1][a_row] = av.y;
        As[nb][a_col + 2][a_row] = av.z;
        As[nb][a_col + 3][a_row] = av.w;
        *(float4*)&Bs[nb][b_row][b_col] = bv;
        __syncthreads();
        buf = nb;
    }

    // epilogue compute on last buffer
#pragma unroll
    for (int kk = 0; kk < 8; kk++) {
        float4 a0 = *(const float4*)&As[buf][kk][ty * 8];
        float4 a1 = *(const float4*)&As[buf][kk][ty * 8 + 4];
        float4 b0 = *(const float4*)&Bs[buf][kk][tx * 8];
        float4 b1 = *(const float4*)&Bs[buf][kk][tx * 8 + 4];
        float ar[8] = {a0.x, a0.y, a0.z, a0.w, a1.x, a1.y, a1.z, a1.w};
        float br[8] = {b0.x, b0.y, b0.z, b0.w, b1.x, b1.y, b1.z, b1.w};
#pragma unroll
        for (int i = 0; i < 8; i++)
#pragma unroll
            for (int j = 0; j < 8; j++)
                acc[i][j] += ar[i] * br[j];
    }

    const int row0 = by * 128 + ty * 8;
    const int col0 = bx * 128 + tx * 8;
    float4 bia0 = *(const float4*)&bias[col0];
    float4 bia1 = *(const float4*)&bias[col0 + 4];
#pragma unroll
    for (int i = 0; i < 8; i++) {
        float4 o0, o1;
        o0.x = acc[i][0] + bia0.x; o0.y = acc[i][1] + bia0.y;
        o0.z = acc[i][2] + bia0.z; o0.w = acc[i][3] + bia0.w;
        o1.x = acc[i][4] + bia1.x; o1.y = acc[i][5] + bia1.y;
        o1.z = acc[i][6] + bia1.z; o1.w = acc[i][7] + bia1.w;
        float* crow = g_xw + (size_t)(row0 + i) * NG + col0;
        *(float4*)(crow)     = o0;
        *(float4*)(crow + 4) = o1;
    }
}

// ---------------------------------------------------------------------------
// K2: peephole LSTM recurrence — 4-CTA clusters.
// Cluster = 4 batch rows x full hidden state. CTA rank r owns hidden units
// [64r, 64r+64). Thread t: batch = t/64 (0..3), local unit = t%64.
// Each thread accumulates all 4 gate pre-activations for its (batch, unit)
// with one float4 weight load per k. New h broadcast to all 4 CTAs' smem via
// st.shared::cluster; one barrier.cluster per step; double-buffered h.
// ---------------------------------------------------------------------------
#define KBPC 4      // batches per cluster
#define CLU  4      // CTAs per cluster

__global__ __launch_bounds__(256, 1) __cluster_dims__(CLU, 1, 1)
void lstm_cluster_kernel(const float*  __restrict__ xw,
                         const float4* __restrict__ rw,     // [H][H] packed
                         const float*  __restrict__ wci_p,
                         const float*  __restrict__ wcf_p,
                         const float*  __restrict__ wco_p,
                         float* __restrict__ hs)
{
    const int tid  = threadIdx.x;
    uint32_t rank;
    asm("mov.u32 %0, %%cluster_ctarank;" : "=r"(rank));
    const int group = blockIdx.x / CLU;
    const int b0    = group * KBPC;

    const int batch = tid >> 6;            // 0..3
    const int ul    = tid & 63;            // local unit
    const int u     = (int)rank * 64 + ul; // global hidden unit

    __shared__ float h_s[2][KBPC][HH];     // 8 KB, double buffered

    // init read-buffer 0 to zeros (own copy only; buf1 fully written at t=0)
    for (int i = tid; i < KBPC * HH; i += 256)
        ((float*)h_s[0])[i] = 0.f;

    float c = 0.f;
    const float wci = wci_p[u];
    const float wcf = wcf_p[u];
    const float wco = wco_p[u];

    // local smem byte-addresses of this thread's h slot in both buffers
    uint32_t laddr0, laddr1;
    {
        uint32_t base;
        asm("{ .reg .u64 t; cvta.to.shared.u64 t, %1; cvt.u32.u64 %0, t; }"
            : "=r"(base) : "l"((void*)&h_s[0][0][0]));
        uint32_t off = (uint32_t)(batch * HH + u) * 4u;
        laddr0 = base + off;
        laddr1 = base + (uint32_t)(KBPC * HH) * 4u + off;
    }

    // all CTAs initialized before anyone writes peers' smem
    asm volatile("barrier.cluster.arrive.aligned;" ::: "memory");
    asm volatile("barrier.cluster.wait.aligned;"   ::: "memory");

    const float4* wp = rw + u;             // stride HH float4 per k

    for (int t = 0; t < TT; t++) {
        const int rb = t & 1;
        const float* xrow = xw + ((size_t)(b0 + batch) * TT + t) * NG;
        float a0 = xrow[u];
        float a1 = xrow[HH + u];
        float a2 = xrow[2 * HH + u];
        float a3 = xrow[3 * HH + u];

        const float4* hb4 = (const float4*)h_s[rb][batch];
#pragma unroll 2
        for (int k4 = 0; k4 < HH / 4; k4++) {
            float4 hv = hb4[k4];                  // broadcast within warp
            float4 w0 = wp[(k4 * 4 + 0) * HH];
            float4 w1 = wp[(k4 * 4 + 1) * HH];
            float4 w2 = wp[(k4 * 4 + 2) * HH];
            float4 w3 = wp[(k4 * 4 + 3) * HH];
            a0 += w0.x * hv.x; a1 += w0.y * hv.x; a2 += w0.z * hv.x; a3 += w0.w * hv.x;
            a0 += w1.x * hv.y; a1 += w1.y * hv.y; a2 += w1.z * hv.y; a3 += w1.w * hv.y;
            a0 += w2.x * hv.z; a1 += w2.y * hv.z; a2 += w2.z * hv.z; a3 += w2.w * hv.z;
            a0 += w3.x * hv.w; a1 += w3.y * hv.w; a2 += w3.z * hv.w; a3 += w3.w * hv.w;
        }

        // gate math (keras order i, f, c, o; peepholes on c_prev / c_new)
        float ig = 1.f / (1.f + __expf(-(a0 + c * wci)));
        float fg = 1.f / (1.f + __expf(-(a1 + c * wcf)));
        float cn = fg * c + ig * tanhf(a2);
        float og = 1.f / (1.f + __expf(-(a3 + cn * wco)));
        float hn = og * tanhf(cn);
        c = cn;

        // broadcast hn into write-buffer of all 4 CTAs in the cluster
        uint32_t wa = (rb ? laddr0 : laddr1);
#pragma unroll
        for (int r = 0; r < CLU; r++) {
            uint32_t ra;
            asm volatile("mapa.shared::cluster.u32 %0, %1, %2;"
                         : "=r"(ra) : "r"(wa), "r"(r));
            asm volatile("st.shared::cluster.f32 [%0], %1;"
                         :: "r"(ra), "f"(hn) : "memory");
        }

        hs[((size_t)(b0 + batch) * TT + t) * HH + u] = hn;

        asm volatile("barrier.cluster.arrive.aligned;" ::: "memory");
        asm volatile("barrier.cluster.wait.aligned;"   ::: "memory");
    }
}

// ---------------------------------------------------------------------------
// K3: BN(inference) -> tanh -> [H x C] dense. One warp per (b,t) row.
// ---------------------------------------------------------------------------
__global__ __launch_bounds__(256)
void head_kernel(const float* __restrict__ hs,
                 const float* __restrict__ gamma,
                 const float* __restrict__ beta,
                 const float* __restrict__ mean,
                 const float* __restrict__ var,
                 const float* __restrict__ fc,     // [H, C]
                 float* __restrict__ out)          // [B*T, C]
{
    const int warp = (blockIdx.x * blockDim.x + threadIdx.x) >> 5;
    const int lane = threadIdx.x & 31;
    if (warp >= BB * TT) return;

    const float* hrow = hs + (size_t)warp * HH;
    float acc[CC];
#pragma unroll
    for (int c = 0; c < CC; c++) acc[c] = 0.f;

#pragma unroll
    for (int kk = 0; kk < HH / 32; kk++) {
        int k = kk * 32 + lane;
        float s = rsqrtf(var[k] + BN_EPS) * gamma[k];
        float v = tanhf((hrow[k] - mean[k]) * s + beta[k]);
#pragma unroll
        for (int c = 0; c < CC; c++)
            acc[c] += v * fc[k * CC + c];
    }
#pragma unroll
    for (int c = 0; c < CC; c++) {
#pragma unroll
        for (int off = 16; off > 0; off >>= 1)
            acc[c] += __shfl_xor_sync(0xffffffffu, acc[c], off);
    }
    if (lane == 0) {
        float* orow = out + (size_t)warp * CC;
#pragma unroll
        for (int c = 0; c < CC; c++) orow[c] = acc[c];
    }
}

// ---------------------------------------------------------------------------
extern "C" void kernel_launch(void* const* d_in, const int* in_sizes, int n_in,
                              void* d_out, int out_size)
{
    const float* x      = (const float*)d_in[0];   // [B,T,F]
    const float* kernel = (const float*)d_in[1];   // [F,4H]
    const float* rec    = (const float*)d_in[2];   // [H,4H]
    const float* bias   = (const float*)d_in[3];   // [4H]
    const float* w_ci   = (const float*)d_in[4];
    const float* w_cf   = (const float*)d_in[5];
    const float* w_co   = (const float*)d_in[6];
    const float* gamma  = (const float*)d_in[7];
    const float* beta   = (const float*)d_in[8];
    const float* mmean  = (const float*)d_in[9];
    const float* mvar   = (const float*)d_in[10];
    const float* fc_w   = (const float*)d_in[11];  // [H,C]
    float* out = (float*)d_out;                    // [B,T,C]

    float*  xw_p;
    float*  hs_p;
    float4* rw_p;
    cudaGetSymbolAddress((void**)&xw_p, g_xw);
    cudaGetSymbolAddress((void**)&hs_p, g_hs);
    cudaGetSymbolAddress((void**)&rw_p, g_rw);

    // K0: pack recurrent weights
    pack_rec_kernel<<<(HH * HH + 255) / 256, 256>>>(rec, rw_p);

    // K1: input projection GEMM
    dim3 g1(NG / 128, (BB * TT) / 128);
    gemm_xw_kernel<<<g1, 256>>>(x, kernel, bias);

    // K2: recurrence, 32 clusters x 4 CTAs x 256 threads
    lstm_cluster_kernel<<<(BB / KBPC) * CLU, 256>>>(xw_p, rw_p, w_ci, w_cf, w_co, hs_p);

    // K3: head, one warp per row
    int rows = BB * TT;
    head_kernel<<<(rows * 32 + 255) / 256, 256>>>(hs_p, gamma, beta, mmean, mvar, fc_w, out);
}

// round 4
// speedup vs baseline: 2.4844x; 1.4885x over previous
#include <cuda_runtime.h>
#include <cuda_bf16.h>
#include <math.h>
#include <stdint.h>

// Problem dims
#define BB   128
#define TT   512
#define FF   784
#define HH   256
#define NG   1024   // 4*H
#define CC   10
#define BN_EPS 1e-3f

// K1 GEMM tiling: 128x128 CTA tile, BK=16 (784 = 49*16)
#define BKC  16
#define NCHK (FF / BKC)   // 49

// Scratch (device globals; no runtime allocation allowed)
__device__ float  g_xw[(size_t)BB * TT * NG];    // 256 MiB
__device__ float  g_hs[(size_t)BB * TT * HH];    //  64 MiB
__device__ float4 g_rw[(size_t)HH * HH];         //   1 MiB packed rec weights
__device__ __nv_bfloat16 g_bhi[(size_t)NG * FF]; // 1.6 MiB: kernel^T hi, [n][k]
__device__ __nv_bfloat16 g_blo[(size_t)NG * FF]; // 1.6 MiB: kernel^T lo

// ---------------------------------------------------------------------------
// helpers
// ---------------------------------------------------------------------------
__device__ __forceinline__ uint32_t smem_u32(const void* p) {
    uint32_t a;
    asm("{ .reg .u64 t; cvta.to.shared.u64 t, %1; cvt.u32.u64 %0, t; }" : "=r"(a) : "l"(p));
    return a;
}
__device__ __forceinline__ void f2bf_hilo(float x, uint16_t& h, uint16_t& l) {
    __nv_bfloat16 hb = __float2bfloat16(x);
    h = __bfloat16_as_ushort(hb);
    l = __bfloat16_as_ushort(__float2bfloat16(x - __bfloat162float(hb)));
}
__device__ __forceinline__ float fsig(float x) {
    return __fdividef(1.f, 1.f + __expf(-x));
}
__device__ __forceinline__ float ftanh(float x) {
    x = fminf(fmaxf(x, -15.f), 15.f);
    float e = __expf(-2.f * x);
    return __fdividef(1.f - e, 1.f + e);
}
__device__ __forceinline__ void mma_bf16(float* d, const uint32_t* a, const uint32_t* b) {
    asm volatile(
        "mma.sync.aligned.m16n8k16.row.col.f32.bf16.bf16.f32 "
        "{%0,%1,%2,%3}, {%4,%5,%6,%7}, {%8,%9}, {%0,%1,%2,%3};"
        : "+f"(d[0]), "+f"(d[1]), "+f"(d[2]), "+f"(d[3])
        : "r"(a[0]), "r"(a[1]), "r"(a[2]), "r"(a[3]), "r"(b[0]), "r"(b[1]));
}

// ---------------------------------------------------------------------------
// K0a: pack rec_kernel [H,4H] -> rw[k][u] float4 {i,f,c,o}
// ---------------------------------------------------------------------------
__global__ void pack_rec_kernel(const float* __restrict__ rec, float4* __restrict__ rw)
{
    int idx = blockIdx.x * blockDim.x + threadIdx.x;
    if (idx >= HH * HH) return;
    int k = idx >> 8;
    int u = idx & 255;
    const float* r = rec + (size_t)k * NG;
    rw[idx] = make_float4(r[u], r[HH + u], r[2 * HH + u], r[3 * HH + u]);
}

// ---------------------------------------------------------------------------
// K0b: split + transpose kernel [F,4H] -> g_bhi/g_blo [n][k] bf16
// ---------------------------------------------------------------------------
__global__ void pack_b_kernel(const float* __restrict__ Bm)
{
    int idx = blockIdx.x * blockDim.x + threadIdx.x;
    if (idx >= NG * FF) return;
    int n = idx / FF;
    int k = idx % FF;
    float v = Bm[(size_t)k * NG + n];
    uint16_t h, l;
    f2bf_hilo(v, h, l);
    g_bhi[idx] = __ushort_as_bfloat16(h);
    g_blo[idx] = __ushort_as_bfloat16(l);
}

// ---------------------------------------------------------------------------
// K1: xw = x @ kernel + bias via mma.sync bf16x3 (hi*hi + hi*lo + lo*hi).
// CTA: 256 threads = 8 warps (4 m x 2 n), warp tile 32x64, BK=16, 49 chunks.
// Smem rows use 48B stride -> conflict-free fragment LDS.
// Single smem buffer + register prefetch of the next chunk.
// ---------------------------------------------------------------------------
#define SROW 48   // bytes per smem row (16 bf16 = 32B used + 16B pad)

__global__ __launch_bounds__(256, 1)
void gemm_mma_kernel(const float* __restrict__ A,     // x: [B*T, FF]
                     const float* __restrict__ bias)  // [NG]
{
    __shared__ __align__(16) char sm[4 * 128 * SROW];   // 24 KB
    char* As_hi = sm;
    char* As_lo = sm + 128 * SROW;
    char* Bs_hi = sm + 2 * 128 * SROW;
    char* Bs_lo = sm + 3 * 128 * SROW;

    const int tid  = threadIdx.x;
    const int lane = tid & 31;
    const int wid  = tid >> 5;
    const int bx   = blockIdx.x;    // n tile (8)
    const int by   = blockIdx.y;    // m tile (512)

    const int m0w = (wid & 3) * 32;   // warp m origin
    const int n0w = (wid >> 2) * 64;  // warp n origin
    const int g   = lane >> 2;        // fragment group row
    const int tq  = lane & 3;         // fragment quad col

    float d[2][8][4];
#pragma unroll
    for (int i = 0; i < 2; i++)
#pragma unroll
        for (int j = 0; j < 8; j++)
#pragma unroll
            for (int q = 0; q < 4; q++) d[i][j][q] = 0.f;

    // staging mapping: thread -> (row 0..127, k-half 0/1)
    const int s_row  = tid >> 1;
    const int s_half = tid & 1;               // k offset 8
    const float* Ag = A + (size_t)(by * 128 + s_row) * FF + s_half * 8;
    const char*  BgH = (const char*)g_bhi + ((size_t)(bx * 128 + s_row) * FF + s_half * 8) * 2;
    const char*  BgL = (const char*)g_blo + ((size_t)(bx * 128 + s_row) * FF + s_half * 8) * 2;
    char* sAh = As_hi + s_row * SROW + s_half * 16;
    char* sAl = As_lo + s_row * SROW + s_half * 16;
    char* sBh = Bs_hi + s_row * SROW + s_half * 16;
    char* sBl = Bs_lo + s_row * SROW + s_half * 16;

    // prefetch chunk 0
    float4 av0 = *(const float4*)(Ag);
    float4 av1 = *(const float4*)(Ag + 4);
    uint4  bvh = *(const uint4*)(BgH);
    uint4  bvl = *(const uint4*)(BgL);

    for (int ic = 0; ic < NCHK; ic++) {
        // ---- STS current prefetched chunk ----
        {
            float f[8] = {av0.x, av0.y, av0.z, av0.w, av1.x, av1.y, av1.z, av1.w};
            uint16_t h[8], l[8];
#pragma unroll
            for (int e = 0; e < 8; e++) f2bf_hilo(f[e], h[e], l[e]);
            uint4 hp, lp;
            hp.x = ((uint32_t)h[1] << 16) | h[0]; hp.y = ((uint32_t)h[3] << 16) | h[2];
            hp.z = ((uint32_t)h[5] << 16) | h[4]; hp.w = ((uint32_t)h[7] << 16) | h[6];
            lp.x = ((uint32_t)l[1] << 16) | l[0]; lp.y = ((uint32_t)l[3] << 16) | l[2];
            lp.z = ((uint32_t)l[5] << 16) | l[4]; lp.w = ((uint32_t)l[7] << 16) | l[6];
            *(uint4*)sAh = hp;
            *(uint4*)sAl = lp;
            *(uint4*)sBh = bvh;
            *(uint4*)sBl = bvl;
        }
        __syncthreads();

        // ---- prefetch next chunk ----
        if (ic + 1 < NCHK) {
            const int k0 = (ic + 1) * BKC;
            av0 = *(const float4*)(Ag + k0);
            av1 = *(const float4*)(Ag + k0 + 4);
            bvh = *(const uint4*)(BgH + (size_t)k0 * 2);
            bvl = *(const uint4*)(BgL + (size_t)k0 * 2);
        }

        // ---- fragments + MMA ----
        uint32_t ah[2][4], al[2][4];
#pragma unroll
        for (int i = 0; i < 2; i++) {
            const char* ab = As_hi + (m0w + i * 16 + g) * SROW + tq * 4;
            ah[i][0] = *(const uint32_t*)(ab);
            ah[i][1] = *(const uint32_t*)(ab + 8 * SROW);
            ah[i][2] = *(const uint32_t*)(ab + 16);
            ah[i][3] = *(const uint32_t*)(ab + 8 * SROW + 16);
            const char* lb = As_lo + (m0w + i * 16 + g) * SROW + tq * 4;
            al[i][0] = *(const uint32_t*)(lb);
            al[i][1] = *(const uint32_t*)(lb + 8 * SROW);
            al[i][2] = *(const uint32_t*)(lb + 16);
            al[i][3] = *(const uint32_t*)(lb + 8 * SROW + 16);
        }
#pragma unroll
        for (int j = 0; j < 8; j++) {
            const char* bb = Bs_hi + (n0w + j * 8 + g) * SROW + tq * 4;
            const char* bl = Bs_lo + (n0w + j * 8 + g) * SROW + tq * 4;
            uint32_t bhf[2], blf[2];
            bhf[0] = *(const uint32_t*)(bb);
            bhf[1] = *(const uint32_t*)(bb + 16);
            blf[0] = *(const uint32_t*)(bl);
            blf[1] = *(const uint32_t*)(bl + 16);
#pragma unroll
            for (int i = 0; i < 2; i++) {
                mma_bf16(d[i][j], ah[i], bhf);   // hi * hi
                mma_bf16(d[i][j], ah[i], blf);   // hi * lo
                mma_bf16(d[i][j], al[i], bhf);   // lo * hi
            }
        }
        __syncthreads();
    }

    // ---- epilogue: + bias -> g_xw ----
#pragma unroll
    for (int j = 0; j < 8; j++) {
        const int col = bx * 128 + n0w + j * 8 + tq * 2;
        const float b0 = bias[col];
        const float b1 = bias[col + 1];
#pragma unroll
        for (int i = 0; i < 2; i++) {
            const int row = by * 128 + m0w + i * 16 + g;
            float2 v0 = make_float2(d[i][j][0] + b0, d[i][j][1] + b1);
            float2 v1 = make_float2(d[i][j][2] + b0, d[i][j][3] + b1);
            *(float2*)(g_xw + (size_t)row * NG + col)       = v0;
            *(float2*)(g_xw + (size_t)(row + 8) * NG + col) = v1;
        }
    }
}

// ---------------------------------------------------------------------------
// K2: peephole LSTM recurrence — 4-CTA clusters (mapa hoisted, unroll 4,
// fast transcendentals).
// ---------------------------------------------------------------------------
#define KBPC 4
#define CLU  4

__global__ __launch_bounds__(256, 1) __cluster_dims__(CLU, 1, 1)
void lstm_cluster_kernel(const float*  __restrict__ xw,
                         const float4* __restrict__ rw,
                         const float*  __restrict__ wci_p,
                         const float*  __restrict__ wcf_p,
                         const float*  __restrict__ wco_p,
                         float* __restrict__ hs)
{
    const int tid  = threadIdx.x;
    uint32_t rank;
    asm("mov.u32 %0, %%cluster_ctarank;" : "=r"(rank));
    const int group = blockIdx.x / CLU;
    const int b0    = group * KBPC;

    const int batch = tid >> 6;
    const int ul    = tid & 63;
    const int u     = (int)rank * 64 + ul;

    __shared__ float h_s[2][KBPC][HH];

    for (int i = tid; i < KBPC * HH; i += 256)
        ((float*)h_s[0])[i] = 0.f;

    float c = 0.f;
    const float wci = wci_p[u];
    const float wcf = wcf_p[u];
    const float wco = wco_p[u];

    // remote smem addresses of my h slot in both buffers, all 4 CTAs (hoisted)
    uint32_t rem0[CLU], rem1[CLU];
    {
        uint32_t base = smem_u32(&h_s[0][0][0]);
        uint32_t off  = (uint32_t)(batch * HH + u) * 4u;
        uint32_t l0 = base + off;
        uint32_t l1 = base + (uint32_t)(KBPC * HH) * 4u + off;
#pragma unroll
        for (int r = 0; r < CLU; r++) {
            asm("mapa.shared::cluster.u32 %0, %1, %2;" : "=r"(rem0[r]) : "r"(l0), "r"(r));
            asm("mapa.shared::cluster.u32 %0, %1, %2;" : "=r"(rem1[r]) : "r"(l1), "r"(r));
        }
    }

    asm volatile("barrier.cluster.arrive.aligned;" ::: "memory");
    asm volatile("barrier.cluster.wait.aligned;"   ::: "memory");

    const float4* wp = rw + u;
    const float* xrow = xw + (size_t)(b0 + batch) * TT * NG;
    float* hrow = hs + (size_t)(b0 + batch) * TT * HH + u;

    for (int t = 0; t < TT; t++) {
        const int rb = t & 1;
        float a0 = xrow[u];
        float a1 = xrow[HH + u];
        float a2 = xrow[2 * HH + u];
        float a3 = xrow[3 * HH + u];

        const float4* hb4 = (const float4*)h_s[rb][batch];
#pragma unroll 4
        for (int k4 = 0; k4 < HH / 4; k4++) {
            float4 hv = hb4[k4];
            float4 w0 = wp[(k4 * 4 + 0) * HH];
            float4 w1 = wp[(k4 * 4 + 1) * HH];
            float4 w2 = wp[(k4 * 4 + 2) * HH];
            float4 w3 = wp[(k4 * 4 + 3) * HH];
            a0 += w0.x * hv.x; a1 += w0.y * hv.x; a2 += w0.z * hv.x; a3 += w0.w * hv.x;
            a0 += w1.x * hv.y; a1 += w1.y * hv.y; a2 += w1.z * hv.y; a3 += w1.w * hv.y;
            a0 += w2.x * hv.z; a1 += w2.y * hv.z; a2 += w2.z * hv.z; a3 += w2.w * hv.z;
            a0 += w3.x * hv.w; a1 += w3.y * hv.w; a2 += w3.z * hv.w; a3 += w3.w * hv.w;
        }

        float ig = fsig(a0 + c * wci);
        float fg = fsig(a1 + c * wcf);
        float cn = fg * c + ig * ftanh(a2);
        float og = fsig(a3 + cn * wco);
        float hn = og * ftanh(cn);
        c = cn;

        const uint32_t* rem = rb ? rem0 : rem1;   // write the other buffer
#pragma unroll
        for (int r = 0; r < CLU; r++)
            asm volatile("st.shared::cluster.f32 [%0], %1;"
                         :: "r"(rem[r]), "f"(hn) : "memory");

        hrow[(size_t)t * HH] = hn;
        xrow += NG;

        asm volatile("barrier.cluster.arrive.aligned;" ::: "memory");
        asm volatile("barrier.cluster.wait.aligned;"   ::: "memory");
    }
}

// ---------------------------------------------------------------------------
// K3: BN(inference) -> tanh -> dense head.
// ---------------------------------------------------------------------------
__global__ __launch_bounds__(256)
void head_kernel(const float* __restrict__ hs,
                 const float* __restrict__ gamma,
                 const float* __restrict__ beta,
                 const float* __restrict__ mean,
                 const float* __restrict__ var,
                 const float* __restrict__ fc,
                 float* __restrict__ out)
{
    const int warp = (blockIdx.x * blockDim.x + threadIdx.x) >> 5;
    const int lane = threadIdx.x & 31;
    if (warp >= BB * TT) return;

    const float* hrow = hs + (size_t)warp * HH;
    float acc[CC];
#pragma unroll
    for (int c = 0; c < CC; c++) acc[c] = 0.f;

#pragma unroll
    for (int kk = 0; kk < HH / 32; kk++) {
        int k = kk * 32 + lane;
        float s = rsqrtf(var[k] + BN_EPS) * gamma[k];
        float v = tanhf((hrow[k] - mean[k]) * s + beta[k]);
#pragma unroll
        for (int c = 0; c < CC; c++)
            acc[c] += v * fc[k * CC + c];
    }
#pragma unroll
    for (int c = 0; c < CC; c++) {
#pragma unroll
        for (int off = 16; off > 0; off >>= 1)
            acc[c] += __shfl_xor_sync(0xffffffffu, acc[c], off);
    }
    if (lane == 0) {
        float* orow = out + (size_t)warp * CC;
#pragma unroll
        for (int c = 0; c < CC; c++) orow[c] = acc[c];
    }
}

// ---------------------------------------------------------------------------
extern "C" void kernel_launch(void* const* d_in, const int* in_sizes, int n_in,
                              void* d_out, int out_size)
{
    const float* x      = (const float*)d_in[0];
    const float* kernel = (const float*)d_in[1];
    const float* rec    = (const float*)d_in[2];
    const float* bias   = (const float*)d_in[3];
    const float* w_ci   = (const float*)d_in[4];
    const float* w_cf   = (const float*)d_in[5];
    const float* w_co   = (const float*)d_in[6];
    const float* gamma  = (const float*)d_in[7];
    const float* beta   = (const float*)d_in[8];
    const float* mmean  = (const float*)d_in[9];
    const float* mvar   = (const float*)d_in[10];
    const float* fc_w   = (const float*)d_in[11];
    float* out = (float*)d_out;

    float*  xw_p;
    float*  hs_p;
    float4* rw_p;
    cudaGetSymbolAddress((void**)&xw_p, g_xw);
    cudaGetSymbolAddress((void**)&hs_p, g_hs);
    cudaGetSymbolAddress((void**)&rw_p, g_rw);

    // K0: packing
    pack_rec_kernel<<<(HH * HH + 255) / 256, 256>>>(rec, rw_p);
    pack_b_kernel<<<((size_t)NG * FF + 255) / 256, 256>>>(kernel);

    // K1: HMMA input-projection GEMM
    dim3 g1(NG / 128, (BB * TT) / 128);
    gemm_mma_kernel<<<g1, 256>>>(x, bias);

    // K2: recurrence, 32 clusters x 4 CTAs
    lstm_cluster_kernel<<<(BB / KBPC) * CLU, 256>>>(xw_p, rw_p, w_ci, w_cf, w_co, hs_p);

    // K3: head
    int rows = BB * TT;
    head_kernel<<<(rows * 32 + 255) / 256, 256>>>(hs_p, gamma, beta, mmean, mvar, fc_w, out);
}